// round 2
// baseline (speedup 1.0000x reference)
#include <cuda_runtime.h>
#include <math.h>

#define N_NODES 100000
#define N_EDGES 600000
#define D 128
#define R 8
#define B_GRAPHS 64
#define L_LAYERS 3

// ---------------- scratch (device globals: no allocation allowed) -------------
__device__ __align__(16) float g_x[N_NODES * D];            // 51.2 MB
__device__ __align__(16) float g_y[N_NODES * D];            // 51.2 MB
__device__ __align__(16) float g_mean[(size_t)N_NODES * R * D]; // 409.6 MB
__device__ float g_inv[N_NODES * R];                        // 3.2 MB (1/max(cnt,1))
__device__ float g_pool[B_GRAPHS * D];
__device__ float g_pcnt[B_GRAPHS];

// ---------------- init / counts ----------------------------------------------
__global__ void k_zero_aux() {
    int i = blockIdx.x * blockDim.x + threadIdx.x;
    int stride = gridDim.x * blockDim.x;
    for (int idx = i; idx < N_NODES * R; idx += stride) g_inv[idx] = 0.f;
    if (i < B_GRAPHS * D) g_pool[i] = 0.f;
    if (i < B_GRAPHS) g_pcnt[i] = 0.f;
}

__global__ void k_count_edges(const int* __restrict__ ei, const int* __restrict__ et) {
    int e = blockIdx.x * blockDim.x + threadIdx.x;
    if (e >= N_EDGES) return;
    int dst = ei[N_EDGES + e];
    int t = et[e];
    atomicAdd(&g_inv[dst * R + t], 1.0f);
}

__global__ void k_finalize_inv() {
    int i = blockIdx.x * blockDim.x + threadIdx.x;
    if (i >= N_NODES * R) return;
    g_inv[i] = 1.0f / fmaxf(g_inv[i], 1.0f);
}

// x = node_emb[node_type]  (float4 vectorized)
__global__ void k_gather(const int* __restrict__ node_type,
                         const float* __restrict__ node_emb) {
    int idx = blockIdx.x * blockDim.x + threadIdx.x;   // over N*32 float4
    if (idx >= N_NODES * (D / 4)) return;
    int n = idx >> 5;
    int f = idx & 31;
    ((float4*)g_x)[idx] =
        ((const float4*)(node_emb + (size_t)node_type[n] * D))[f];
}

__global__ void k_zero_mean() {
    size_t i = (size_t)blockIdx.x * blockDim.x + threadIdx.x;
    size_t stride = (size_t)gridDim.x * blockDim.x;
    size_t total = (size_t)N_NODES * R * D / 4;
    float4 z = make_float4(0.f, 0.f, 0.f, 0.f);
    for (size_t idx = i; idx < total; idx += stride)
        ((float4*)g_mean)[idx] = z;
}

// ---------------- scatter: mean[(dst,rel)] += x[src] * inv_cnt ----------------
// one warp per edge; warp covers the 128-float row (float4 per lane)
__global__ void k_scatter(int flip, const int* __restrict__ ei,
                          const int* __restrict__ et) {
    const float* xin = flip ? g_y : g_x;
    int w = (blockIdx.x * blockDim.x + threadIdx.x) >> 5;
    int lane = threadIdx.x & 31;
    if (w >= N_EDGES) return;
    int src = ei[w];
    int dst = ei[N_EDGES + w];
    int t = et[w];
    int seg = dst * R + t;
    float sc = g_inv[seg];
    float4 v = ((const float4*)(xin + (size_t)src * D))[lane];
    float* m = g_mean + (size_t)seg * D + lane * 4;
    atomicAdd(m + 0, v.x * sc);
    atomicAdd(m + 1, v.y * sc);
    atomicAdd(m + 2, v.z * sc);
    atomicAdd(m + 3, v.w * sc);
}

// ---------------- layer GEMM: out = relu([mean|x] @ [Wrel;Wroot] + bias) ------
// M=100000, N=128, K=1152 (64 chunks of 16 from mean, 8 from x). fp32 SGEMM,
// 128x128 tile, 256 threads, 8x8 per thread.
__global__ void __launch_bounds__(256)
k_gemm(int flip, const float* __restrict__ Wrel, const float* __restrict__ Wroot,
       const float* __restrict__ bias) {
    const float* xin = flip ? g_y : g_x;
    float* xout = flip ? g_x : g_y;

    __shared__ float As[16][132];   // [k][m], padded
    __shared__ float Bs[16][128];   // [k][n]

    int tid = threadIdx.x;
    int tx = tid & 15;              // col group
    int ty = tid >> 4;              // row group
    int row0 = blockIdx.x * 128;

    float acc[8][8];
#pragma unroll
    for (int i = 0; i < 8; i++)
#pragma unroll
        for (int j = 0; j < 8; j++) acc[i][j] = 0.f;

    for (int kb = 0; kb < 72; kb++) {
        // load A tile (128 rows x 16 k), store transposed
#pragma unroll
        for (int h = 0; h < 2; h++) {
            int q = tid + h * 256;          // float4 id in [0,512)
            int m = q >> 2;
            int k4 = q & 3;
            int row = row0 + m;
            float4 v = make_float4(0.f, 0.f, 0.f, 0.f);
            if (row < N_NODES) {
                if (kb < 64)
                    v = *(const float4*)(g_mean + (size_t)row * (R * D) + kb * 16 + k4 * 4);
                else
                    v = *(const float4*)(xin + (size_t)row * D + (kb - 64) * 16 + k4 * 4);
            }
            As[k4 * 4 + 0][m] = v.x;
            As[k4 * 4 + 1][m] = v.y;
            As[k4 * 4 + 2][m] = v.z;
            As[k4 * 4 + 3][m] = v.w;
        }
        // load B tile (16 k x 128 n)
#pragma unroll
        for (int h = 0; h < 2; h++) {
            int q = tid + h * 256;
            int k = q >> 5;
            int n4 = q & 31;
            const float* Bsrc = (kb < 64)
                ? (Wrel + (size_t)(kb * 16 + k) * D + n4 * 4)
                : (Wroot + (size_t)((kb - 64) * 16 + k) * D + n4 * 4);
            *(float4*)&Bs[k][n4 * 4] = *(const float4*)Bsrc;
        }
        __syncthreads();

#pragma unroll
        for (int k = 0; k < 16; k++) {
            float a[8], bv[8];
            *(float4*)(a + 0) = *(float4*)&As[k][ty * 8 + 0];
            *(float4*)(a + 4) = *(float4*)&As[k][ty * 8 + 4];
            *(float4*)(bv + 0) = *(float4*)&Bs[k][tx * 8 + 0];
            *(float4*)(bv + 4) = *(float4*)&Bs[k][tx * 8 + 4];
#pragma unroll
            for (int i = 0; i < 8; i++)
#pragma unroll
                for (int j = 0; j < 8; j++) acc[i][j] += a[i] * bv[j];
        }
        __syncthreads();
    }

    // epilogue: + bias, relu, store
#pragma unroll
    for (int i = 0; i < 8; i++) {
        int row = row0 + ty * 8 + i;
        if (row >= N_NODES) break;
        float4 o0, o1;
        float* op = (float*)&o0;
#pragma unroll
        for (int j = 0; j < 4; j++)
            op[j] = fmaxf(acc[i][j] + bias[tx * 8 + j], 0.f);
        op = (float*)&o1;
#pragma unroll
        for (int j = 0; j < 4; j++)
            op[j] = fmaxf(acc[i][4 + j] + bias[tx * 8 + 4 + j], 0.f);
        *(float4*)(xout + (size_t)row * D + tx * 8 + 0) = o0;
        *(float4*)(xout + (size_t)row * D + tx * 8 + 4) = o1;
    }
}

// ---------------- global mean pool (batch is sorted) --------------------------
// 128 threads (one per feature dim), 256 nodes per block.
__global__ void k_pool(const int* __restrict__ batch) {
    const float* x = g_y;               // final activations after layer 2
    int d = threadIdx.x;                // 128 threads == D
    int start = blockIdx.x * 256;
    if (start >= N_NODES) return;
    int end = min(start + 256, N_NODES);
    float acc = 0.f, c = 0.f;
    int curb = batch[start];
    for (int n = start; n < end; n++) {
        int bb = batch[n];
        if (bb != curb) {
            atomicAdd(&g_pool[curb * D + d], acc);
            if (d == 0) atomicAdd(&g_pcnt[curb], c);
            acc = 0.f; c = 0.f; curb = bb;
        }
        acc += x[(size_t)n * D + d];
        c += 1.f;
    }
    atomicAdd(&g_pool[curb * D + d], acc);
    if (d == 0) atomicAdd(&g_pcnt[curb], c);
}

// ---------------- MLP heads ---------------------------------------------------
__global__ void k_head(const float* __restrict__ rw1, const float* __restrict__ rb1,
                       const float* __restrict__ rw2, const float* __restrict__ rb2,
                       const float* __restrict__ sw1, const float* __restrict__ sb1,
                       const float* __restrict__ sw2, const float* __restrict__ sb2,
                       float* __restrict__ out) {
    int b = blockIdx.x;
    int j = threadIdx.x;                // 128 threads
    __shared__ float gv[128];
    __shared__ float red[4];
    float inv = 1.f / fmaxf(g_pcnt[b], 1.f);
    gv[j] = g_pool[b * D + j] * inv;
    __syncthreads();

#pragma unroll
    for (int head = 0; head < 2; head++) {
        const float* W1 = head ? sw1 : rw1;
        const float* B1 = head ? sb1 : rb1;
        const float* W2 = head ? sw2 : rw2;
        const float* B2 = head ? sb2 : rb2;
        float h = B1[j];
#pragma unroll 8
        for (int d = 0; d < D; d++) h += gv[d] * W1[d * D + j];
        h = fmaxf(h, 0.f);
        float p = h * W2[j];
#pragma unroll
        for (int o = 16; o > 0; o >>= 1) p += __shfl_down_sync(0xffffffffu, p, o);
        if ((j & 31) == 0) red[j >> 5] = p;
        __syncthreads();
        if (j == 0) out[head * B_GRAPHS + b] = red[0] + red[1] + red[2] + red[3] + B2[0];
        __syncthreads();
    }
}

// ---------------- launch ------------------------------------------------------
extern "C" void kernel_launch(void* const* d_in, const int* in_sizes, int n_in,
                              void* d_out, int out_size) {
    const int* node_type = (const int*)d_in[0];
    const int* edge_index = (const int*)d_in[1];
    const int* edge_type = (const int*)d_in[2];
    const int* batch = (const int*)d_in[3];
    const float* node_emb = (const float*)d_in[4];
    const float* rel_w = (const float*)d_in[5];
    const float* root_w = (const float*)d_in[6];
    const float* bias = (const float*)d_in[7];
    const float* risk_w1 = (const float*)d_in[8];
    const float* risk_b1 = (const float*)d_in[9];
    const float* risk_w2 = (const float*)d_in[10];
    const float* risk_b2 = (const float*)d_in[11];
    const float* safe_w1 = (const float*)d_in[12];
    const float* safe_b1 = (const float*)d_in[13];
    const float* safe_w2 = (const float*)d_in[14];
    const float* safe_b2 = (const float*)d_in[15];
    float* out = (float*)d_out;

    // counts / init (per call; deterministic)
    k_zero_aux<<<(N_NODES * R + 255) / 256, 256>>>();
    k_count_edges<<<(N_EDGES + 255) / 256, 256>>>(edge_index, edge_type);
    k_finalize_inv<<<(N_NODES * R + 255) / 256, 256>>>();
    k_gather<<<(N_NODES * (D / 4) + 255) / 256, 256>>>(node_type, node_emb);

    for (int l = 0; l < L_LAYERS; l++) {
        int flip = l & 1;   // 0: in g_x -> out g_y ; 1: in g_y -> out g_x
        k_zero_mean<<<2048, 256>>>();
        k_scatter<<<(N_EDGES * 32 + 255) / 256, 256>>>(flip, edge_index, edge_type);
        k_gemm<<<(N_NODES + 127) / 128, 256>>>(
            flip,
            rel_w + (size_t)l * R * D * D,
            root_w + (size_t)l * D * D,
            bias + (size_t)l * D);
    }

    k_pool<<<(N_NODES + 255) / 256, 128>>>(batch);   // 128 threads == D (bugfix)
    k_head<<<B_GRAPHS, 128>>>(risk_w1, risk_b1, risk_w2, risk_b2,
                              safe_w1, safe_b1, safe_w2, safe_b2, out);
}

// round 3
// speedup vs baseline: 2.6825x; 2.6825x over previous
#include <cuda_runtime.h>
#include <math.h>
#include <stdint.h>

#define N_NODES 100000
#define N_EDGES 600000
#define D 128
#define R 8
#define B_GRAPHS 64
#define L_LAYERS 3

// ---------------- scratch (device globals: no allocation allowed) -------------
__device__ __align__(16) float g_x[N_NODES * D];            // 51.2 MB
__device__ __align__(16) float g_y[N_NODES * D];            // 51.2 MB
__device__ __align__(16) float g_mean[(size_t)N_NODES * R * D]; // 409.6 MB
__device__ float g_inv[N_NODES * R];                        // 3.2 MB (1/max(cnt,1))
__device__ float g_pool[B_GRAPHS * D];
__device__ float g_pcnt[B_GRAPHS];

// ---------------- init / counts ----------------------------------------------
__global__ void k_zero_aux() {
    int i = blockIdx.x * blockDim.x + threadIdx.x;
    int stride = gridDim.x * blockDim.x;
    for (int idx = i; idx < N_NODES * R; idx += stride) g_inv[idx] = 0.f;
    if (i < B_GRAPHS * D) g_pool[i] = 0.f;
    if (i < B_GRAPHS) g_pcnt[i] = 0.f;
}

__global__ void k_count_edges(const int* __restrict__ ei, const int* __restrict__ et) {
    int e = blockIdx.x * blockDim.x + threadIdx.x;
    if (e >= N_EDGES) return;
    int dst = ei[N_EDGES + e];
    int t = et[e];
    atomicAdd(&g_inv[dst * R + t], 1.0f);
}

__global__ void k_finalize_inv() {
    int i = blockIdx.x * blockDim.x + threadIdx.x;
    if (i >= N_NODES * R) return;
    g_inv[i] = 1.0f / fmaxf(g_inv[i], 1.0f);
}

// x = node_emb[node_type]  (float4 vectorized)
__global__ void k_gather(const int* __restrict__ node_type,
                         const float* __restrict__ node_emb) {
    int idx = blockIdx.x * blockDim.x + threadIdx.x;   // over N*32 float4
    if (idx >= N_NODES * (D / 4)) return;
    int n = idx >> 5;
    int f = idx & 31;
    ((float4*)g_x)[idx] =
        ((const float4*)(node_emb + (size_t)node_type[n] * D))[f];
}

__global__ void k_zero_mean() {
    size_t i = (size_t)blockIdx.x * blockDim.x + threadIdx.x;
    size_t stride = (size_t)gridDim.x * blockDim.x;
    size_t total = (size_t)N_NODES * R * D / 4;
    float4 z = make_float4(0.f, 0.f, 0.f, 0.f);
    for (size_t idx = i; idx < total; idx += stride)
        ((float4*)g_mean)[idx] = z;
}

// ---------------- scatter: mean[(dst,rel)] += x[src] * inv_cnt ----------------
// one warp per edge; lane covers one float4; single RED.128 per lane
__global__ void k_scatter(int flip, const int* __restrict__ ei,
                          const int* __restrict__ et) {
    const float* xin = flip ? g_y : g_x;
    int w = (blockIdx.x * blockDim.x + threadIdx.x) >> 5;
    int lane = threadIdx.x & 31;
    if (w >= N_EDGES) return;
    int src = ei[w];
    int dst = ei[N_EDGES + w];
    int t = et[w];
    int seg = dst * R + t;
    float sc = g_inv[seg];
    float4 v = ((const float4*)(xin + (size_t)src * D))[lane];
    v.x *= sc; v.y *= sc; v.z *= sc; v.w *= sc;
    float4* m = (float4*)(g_mean + (size_t)seg * D) + lane;
    atomicAdd(m, v);    // sm_90+: RED.E.ADD.F32.128
}

// ---------------- layer GEMM: out = relu([mean|x] @ [Wrel;Wroot] + bias) ------
// tf32 mma.sync.m16n8k8. M=100000, N=128, K=1152. 128x128 tile, 8 warps,
// each warp 64x32. A staged [m][k] stride 20 (conflict-free), B [k][n] stride 136.
#define SA_STRIDE 20
#define SB_STRIDE 136

__device__ __forceinline__ uint32_t f2tf32(float x) {
    uint32_t r;
    asm("cvt.rna.tf32.f32 %0, %1;" : "=r"(r) : "f"(x));
    return r;
}

__global__ void __launch_bounds__(256)
k_gemm(int flip, const float* __restrict__ Wrel, const float* __restrict__ Wroot,
       const float* __restrict__ bias) {
    const float* xin = flip ? g_y : g_x;
    float* xout = flip ? g_x : g_y;

    __shared__ uint32_t sA[128 * SA_STRIDE];   // 10240 B
    __shared__ uint32_t sB[16 * SB_STRIDE];    // 8704 B
    __shared__ float sBias[128];

    int tid = threadIdx.x;
    int lane = tid & 31;
    int w = tid >> 5;
    int g = lane >> 2;          // 0..7
    int tg = lane & 3;          // 0..3
    int rm = (w & 1) * 64;      // warp row base within tile
    int cn = (w >> 1) * 32;     // warp col base within tile
    int row0 = blockIdx.x * 128;

    if (tid < 128) sBias[tid] = bias[tid];

    float acc[4][4][4];
#pragma unroll
    for (int mi = 0; mi < 4; mi++)
#pragma unroll
        for (int ni = 0; ni < 4; ni++)
#pragma unroll
            for (int c = 0; c < 4; c++) acc[mi][ni][c] = 0.f;

    for (int kb = 0; kb < 72; kb++) {
        // ---- stage A tile: 128 rows x 16 k (512 float4 loads) ----
#pragma unroll
        for (int h = 0; h < 2; h++) {
            int q = tid + h * 256;          // float4 id in [0,512)
            int m = q >> 2;
            int k4 = q & 3;
            int row = row0 + m;
            float4 v = make_float4(0.f, 0.f, 0.f, 0.f);
            if (row < N_NODES) {
                if (kb < 64)
                    v = *(const float4*)(g_mean + (size_t)row * (R * D) + kb * 16 + k4 * 4);
                else
                    v = *(const float4*)(xin + (size_t)row * D + (kb - 64) * 16 + k4 * 4);
            }
            uint4 t4;
            t4.x = f2tf32(v.x); t4.y = f2tf32(v.y);
            t4.z = f2tf32(v.z); t4.w = f2tf32(v.w);
            ((uint4*)(sA + m * SA_STRIDE))[k4] = t4;   // 80B row stride: aligned
        }
        // ---- stage B tile: 16 k x 128 n ----
#pragma unroll
        for (int h = 0; h < 2; h++) {
            int q = tid + h * 256;
            int k = q >> 5;
            int n4 = q & 31;
            const float* Bsrc = (kb < 64)
                ? (Wrel + (size_t)(kb * 16 + k) * D + n4 * 4)
                : (Wroot + (size_t)((kb - 64) * 16 + k) * D + n4 * 4);
            float4 v = *(const float4*)Bsrc;
            uint4 t4;
            t4.x = f2tf32(v.x); t4.y = f2tf32(v.y);
            t4.z = f2tf32(v.z); t4.w = f2tf32(v.w);
            ((uint4*)(sB + k * SB_STRIDE))[n4] = t4;   // 544B row stride: aligned
        }
        __syncthreads();

        // ---- 2 k-steps of 8 ----
#pragma unroll
        for (int kk = 0; kk < 16; kk += 8) {
            uint32_t af[4][4];
#pragma unroll
            for (int mi = 0; mi < 4; mi++) {
                int mrow = rm + mi * 16 + g;
                af[mi][0] = sA[mrow * SA_STRIDE + kk + tg];
                af[mi][1] = sA[(mrow + 8) * SA_STRIDE + kk + tg];
                af[mi][2] = sA[mrow * SA_STRIDE + kk + tg + 4];
                af[mi][3] = sA[(mrow + 8) * SA_STRIDE + kk + tg + 4];
            }
            uint32_t bf[4][2];
#pragma unroll
            for (int ni = 0; ni < 4; ni++) {
                int ncol = cn + ni * 8 + g;
                bf[ni][0] = sB[(kk + tg) * SB_STRIDE + ncol];
                bf[ni][1] = sB[(kk + tg + 4) * SB_STRIDE + ncol];
            }
#pragma unroll
            for (int mi = 0; mi < 4; mi++)
#pragma unroll
                for (int ni = 0; ni < 4; ni++) {
                    asm volatile(
                        "mma.sync.aligned.m16n8k8.row.col.f32.tf32.tf32.f32 "
                        "{%0,%1,%2,%3}, {%4,%5,%6,%7}, {%8,%9}, {%0,%1,%2,%3};"
                        : "+f"(acc[mi][ni][0]), "+f"(acc[mi][ni][1]),
                          "+f"(acc[mi][ni][2]), "+f"(acc[mi][ni][3])
                        : "r"(af[mi][0]), "r"(af[mi][1]),
                          "r"(af[mi][2]), "r"(af[mi][3]),
                          "r"(bf[ni][0]), "r"(bf[ni][1]));
                }
        }
        __syncthreads();
    }

    // ---- epilogue: + bias, relu, store ----
#pragma unroll
    for (int mi = 0; mi < 4; mi++) {
#pragma unroll
        for (int ni = 0; ni < 4; ni++) {
            int col = cn + ni * 8 + 2 * tg;
            int row1 = row0 + rm + mi * 16 + g;
            int row2 = row1 + 8;
            float b0 = sBias[col], b1 = sBias[col + 1];
            if (row1 < N_NODES) {
                float2 o;
                o.x = fmaxf(acc[mi][ni][0] + b0, 0.f);
                o.y = fmaxf(acc[mi][ni][1] + b1, 0.f);
                *(float2*)(xout + (size_t)row1 * D + col) = o;
            }
            if (row2 < N_NODES) {
                float2 o;
                o.x = fmaxf(acc[mi][ni][2] + b0, 0.f);
                o.y = fmaxf(acc[mi][ni][3] + b1, 0.f);
                *(float2*)(xout + (size_t)row2 * D + col) = o;
            }
        }
    }
}

// ---------------- global mean pool (batch is sorted) --------------------------
// 128 threads (one per feature dim), 256 nodes per block.
__global__ void k_pool(const int* __restrict__ batch) {
    const float* x = g_y;               // final activations after layer 2
    int d = threadIdx.x;                // 128 threads == D
    int start = blockIdx.x * 256;
    if (start >= N_NODES) return;
    int end = min(start + 256, N_NODES);
    float acc = 0.f, c = 0.f;
    int curb = batch[start];
    for (int n = start; n < end; n++) {
        int bb = batch[n];
        if (bb != curb) {
            atomicAdd(&g_pool[curb * D + d], acc);
            if (d == 0) atomicAdd(&g_pcnt[curb], c);
            acc = 0.f; c = 0.f; curb = bb;
        }
        acc += x[(size_t)n * D + d];
        c += 1.f;
    }
    atomicAdd(&g_pool[curb * D + d], acc);
    if (d == 0) atomicAdd(&g_pcnt[curb], c);
}

// ---------------- MLP heads ---------------------------------------------------
__global__ void k_head(const float* __restrict__ rw1, const float* __restrict__ rb1,
                       const float* __restrict__ rw2, const float* __restrict__ rb2,
                       const float* __restrict__ sw1, const float* __restrict__ sb1,
                       const float* __restrict__ sw2, const float* __restrict__ sb2,
                       float* __restrict__ out) {
    int b = blockIdx.x;
    int j = threadIdx.x;                // 128 threads
    __shared__ float gv[128];
    __shared__ float red[4];
    float inv = 1.f / fmaxf(g_pcnt[b], 1.f);
    gv[j] = g_pool[b * D + j] * inv;
    __syncthreads();

#pragma unroll
    for (int head = 0; head < 2; head++) {
        const float* W1 = head ? sw1 : rw1;
        const float* B1 = head ? sb1 : rb1;
        const float* W2 = head ? sw2 : rw2;
        const float* B2 = head ? sb2 : rb2;
        float h = B1[j];
#pragma unroll 8
        for (int d = 0; d < D; d++) h += gv[d] * W1[d * D + j];
        h = fmaxf(h, 0.f);
        float p = h * W2[j];
#pragma unroll
        for (int o = 16; o > 0; o >>= 1) p += __shfl_down_sync(0xffffffffu, p, o);
        if ((j & 31) == 0) red[j >> 5] = p;
        __syncthreads();
        if (j == 0) out[head * B_GRAPHS + b] = red[0] + red[1] + red[2] + red[3] + B2[0];
        __syncthreads();
    }
}

// ---------------- launch ------------------------------------------------------
extern "C" void kernel_launch(void* const* d_in, const int* in_sizes, int n_in,
                              void* d_out, int out_size) {
    const int* node_type = (const int*)d_in[0];
    const int* edge_index = (const int*)d_in[1];
    const int* edge_type = (const int*)d_in[2];
    const int* batch = (const int*)d_in[3];
    const float* node_emb = (const float*)d_in[4];
    const float* rel_w = (const float*)d_in[5];
    const float* root_w = (const float*)d_in[6];
    const float* bias = (const float*)d_in[7];
    const float* risk_w1 = (const float*)d_in[8];
    const float* risk_b1 = (const float*)d_in[9];
    const float* risk_w2 = (const float*)d_in[10];
    const float* risk_b2 = (const float*)d_in[11];
    const float* safe_w1 = (const float*)d_in[12];
    const float* safe_b1 = (const float*)d_in[13];
    const float* safe_w2 = (const float*)d_in[14];
    const float* safe_b2 = (const float*)d_in[15];
    float* out = (float*)d_out;

    // counts / init (per call; deterministic)
    k_zero_aux<<<(N_NODES * R + 255) / 256, 256>>>();
    k_count_edges<<<(N_EDGES + 255) / 256, 256>>>(edge_index, edge_type);
    k_finalize_inv<<<(N_NODES * R + 255) / 256, 256>>>();
    k_gather<<<(N_NODES * (D / 4) + 255) / 256, 256>>>(node_type, node_emb);

    for (int l = 0; l < L_LAYERS; l++) {
        int flip = l & 1;   // 0: in g_x -> out g_y ; 1: in g_y -> out g_x
        k_zero_mean<<<2048, 256>>>();
        k_scatter<<<(N_EDGES * 32 + 255) / 256, 256>>>(flip, edge_index, edge_type);
        k_gemm<<<(N_NODES + 127) / 128, 256>>>(
            flip,
            rel_w + (size_t)l * R * D * D,
            root_w + (size_t)l * D * D,
            bias + (size_t)l * D);
    }

    k_pool<<<(N_NODES + 255) / 256, 128>>>(batch);
    k_head<<<B_GRAPHS, 128>>>(risk_w1, risk_b1, risk_w2, risk_b2,
                              safe_w1, safe_b1, safe_w2, safe_b2, out);
}

// round 4
// speedup vs baseline: 4.5412x; 1.6929x over previous
#include <cuda_runtime.h>
#include <math.h>
#include <stdint.h>

#define N_NODES 100000
#define N_EDGES 600000
#define D 128
#define R 8
#define B_GRAPHS 64
#define L_LAYERS 3

#define EPAD_CAP 601088            // >= E + R*128, multiple of 128
#define NBLK_EDGE (EPAD_CAP / 128) // 4696

// ---------------- scratch (device globals) ------------------------------------
__device__ __align__(16) float g_x[N_NODES * D];      // 51.2 MB (L2-resident)
__device__ __align__(16) float g_y[N_NODES * D];      // 51.2 MB (L2-resident)
__device__ float g_inv[N_NODES * R];                  // 1/max(cnt,1)
__device__ int   g_esrc[EPAD_CAP];
__device__ int   g_edst[EPAD_CAP];
__device__ float g_escale[EPAD_CAP];                  // 0 for padding slots
__device__ int   g_rcnt[R];
__device__ int   g_cur[R];
__device__ int   g_poff[R + 1];                       // padded bucket offsets
__device__ float g_pool[B_GRAPHS * D];
__device__ float g_pcnt[B_GRAPHS];

// ---------------- init ---------------------------------------------------------
__global__ void k_init() {
    int i = blockIdx.x * blockDim.x + threadIdx.x;
    int stride = gridDim.x * blockDim.x;
    for (int idx = i; idx < N_NODES * R; idx += stride) g_inv[idx] = 0.f;
    if (i < R) { g_rcnt[i] = 0; g_cur[i] = 0; }
    if (i < B_GRAPHS * D) g_pool[i] = 0.f;
    if (i < B_GRAPHS) g_pcnt[i] = 0.f;
}

__global__ void k_prefill() {
    int i = blockIdx.x * blockDim.x + threadIdx.x;
    if (i >= EPAD_CAP) return;
    g_esrc[i] = 0; g_edst[i] = 0; g_escale[i] = 0.f;
}

// counts per (dst,rel) + per-relation histogram (warp-aggregated)
__global__ void k_count(const int* __restrict__ ei, const int* __restrict__ et) {
    int e = blockIdx.x * blockDim.x + threadIdx.x;
    bool act = e < N_EDGES;
    unsigned amask = __ballot_sync(0xffffffffu, act);
    if (!act) return;
    int t = et[e];
    int dst = ei[N_EDGES + e];
    atomicAdd(&g_inv[dst * R + t], 1.0f);
    unsigned m = __match_any_sync(amask, t);
    int lane = threadIdx.x & 31;
    int leader = __ffs(m) - 1;
    if (lane == leader) atomicAdd(&g_rcnt[t], __popc(m));
}

__global__ void k_finalize_inv() {
    int i = blockIdx.x * blockDim.x + threadIdx.x;
    if (i >= N_NODES * R) return;
    g_inv[i] = 1.0f / fmaxf(g_inv[i], 1.0f);
}

__global__ void k_offsets() {
    if (threadIdx.x == 0) {
        int off = 0;
#pragma unroll
        for (int r = 0; r < R; r++) {
            g_poff[r] = off;
            off += ((g_rcnt[r] + 127) >> 7) << 7;
        }
        g_poff[R] = off;
    }
}

// counting-sort edges into padded relation buckets
__global__ void k_sort(const int* __restrict__ ei, const int* __restrict__ et) {
    int e = blockIdx.x * blockDim.x + threadIdx.x;
    bool act = e < N_EDGES;
    unsigned amask = __ballot_sync(0xffffffffu, act);
    if (!act) return;
    int t = et[e];
    int src = ei[e];
    int dst = ei[N_EDGES + e];
    unsigned m = __match_any_sync(amask, t);
    int lane = threadIdx.x & 31;
    int leader = __ffs(m) - 1;
    int base = 0;
    if (lane == leader) base = atomicAdd(&g_cur[t], __popc(m));
    base = __shfl_sync(m, base, leader);
    int rank = __popc(m & ((1u << lane) - 1));
    int pos = g_poff[t] + base + rank;
    g_esrc[pos] = src;
    g_edst[pos] = dst;
    g_escale[pos] = g_inv[dst * R + t];
}

// x = node_emb[node_type]
__global__ void k_gather(const int* __restrict__ node_type,
                         const float* __restrict__ node_emb) {
    int idx = blockIdx.x * blockDim.x + threadIdx.x;
    if (idx >= N_NODES * (D / 4)) return;
    int n = idx >> 5;
    int f = idx & 31;
    ((float4*)g_x)[idx] =
        ((const float4*)(node_emb + (size_t)node_type[n] * D))[f];
}

// ---------------- tf32 helpers --------------------------------------------------
#define SA_STRIDE 20
#define SB_STRIDE 136

__device__ __forceinline__ uint32_t f2tf32(float x) {
    uint32_t r;
    asm("cvt.rna.tf32.f32 %0, %1;" : "=r"(r) : "f"(x));
    return r;
}

#define MMA_TF32(ac, a0, a1, a2, a3, b0, b1)                                   \
    asm volatile(                                                              \
        "mma.sync.aligned.m16n8k8.row.col.f32.tf32.tf32.f32 "                  \
        "{%0,%1,%2,%3}, {%4,%5,%6,%7}, {%8,%9}, {%0,%1,%2,%3};"                \
        : "+f"((ac)[0]), "+f"((ac)[1]), "+f"((ac)[2]), "+f"((ac)[3])           \
        : "r"(a0), "r"(a1), "r"(a2), "r"(a3), "r"(b0), "r"(b1))

// ---------------- root: y = x_eff @ Wroot + bias (x_eff = relu(x) if dorelu) ----
__global__ void __launch_bounds__(256)
k_root(int flip, int dorelu, const float* __restrict__ W,
       const float* __restrict__ bias) {
    const float* xin = flip ? g_y : g_x;
    float* yout = flip ? g_x : g_y;

    __shared__ uint32_t sA[128 * SA_STRIDE];
    __shared__ uint32_t sB[16 * SB_STRIDE];
    __shared__ float sBias[128];

    int tid = threadIdx.x;
    int lane = tid & 31;
    int w = tid >> 5;
    int g = lane >> 2, tg = lane & 3;
    int rm = (w & 1) * 64, cn = (w >> 1) * 32;
    int row0 = blockIdx.x * 128;

    if (tid < 128) sBias[tid] = bias[tid];

    float acc[4][4][4];
#pragma unroll
    for (int mi = 0; mi < 4; mi++)
#pragma unroll
        for (int ni = 0; ni < 4; ni++)
#pragma unroll
            for (int c = 0; c < 4; c++) acc[mi][ni][c] = 0.f;

    for (int kb = 0; kb < 8; kb++) {
#pragma unroll
        for (int h = 0; h < 2; h++) {
            int q = tid + h * 256;
            int m = q >> 2, k4 = q & 3;
            int row = row0 + m;
            float4 v = make_float4(0.f, 0.f, 0.f, 0.f);
            if (row < N_NODES)
                v = *(const float4*)(xin + (size_t)row * D + kb * 16 + k4 * 4);
            if (dorelu) {
                v.x = fmaxf(v.x, 0.f); v.y = fmaxf(v.y, 0.f);
                v.z = fmaxf(v.z, 0.f); v.w = fmaxf(v.w, 0.f);
            }
            uint4 t4 = {f2tf32(v.x), f2tf32(v.y), f2tf32(v.z), f2tf32(v.w)};
            ((uint4*)(sA + m * SA_STRIDE))[k4] = t4;
        }
#pragma unroll
        for (int h = 0; h < 2; h++) {
            int q = tid + h * 256;
            int k = q >> 5, n4 = q & 31;
            float4 v = *(const float4*)(W + (size_t)(kb * 16 + k) * D + n4 * 4);
            uint4 t4 = {f2tf32(v.x), f2tf32(v.y), f2tf32(v.z), f2tf32(v.w)};
            ((uint4*)(sB + k * SB_STRIDE))[n4] = t4;
        }
        __syncthreads();
#pragma unroll
        for (int kk = 0; kk < 16; kk += 8) {
            uint32_t af[4][4];
#pragma unroll
            for (int mi = 0; mi < 4; mi++) {
                int mrow = rm + mi * 16 + g;
                af[mi][0] = sA[mrow * SA_STRIDE + kk + tg];
                af[mi][1] = sA[(mrow + 8) * SA_STRIDE + kk + tg];
                af[mi][2] = sA[mrow * SA_STRIDE + kk + tg + 4];
                af[mi][3] = sA[(mrow + 8) * SA_STRIDE + kk + tg + 4];
            }
            uint32_t bf[4][2];
#pragma unroll
            for (int ni = 0; ni < 4; ni++) {
                int ncol = cn + ni * 8 + g;
                bf[ni][0] = sB[(kk + tg) * SB_STRIDE + ncol];
                bf[ni][1] = sB[(kk + tg + 4) * SB_STRIDE + ncol];
            }
#pragma unroll
            for (int mi = 0; mi < 4; mi++)
#pragma unroll
                for (int ni = 0; ni < 4; ni++)
                    MMA_TF32(acc[mi][ni], af[mi][0], af[mi][1], af[mi][2],
                             af[mi][3], bf[ni][0], bf[ni][1]);
        }
        __syncthreads();
    }

#pragma unroll
    for (int mi = 0; mi < 4; mi++)
#pragma unroll
        for (int ni = 0; ni < 4; ni++) {
            int col = cn + ni * 8 + 2 * tg;
            int row1 = row0 + rm + mi * 16 + g;
            int row2 = row1 + 8;
            float b0 = sBias[col], b1 = sBias[col + 1];
            if (row1 < N_NODES) {
                float2 o = {acc[mi][ni][0] + b0, acc[mi][ni][1] + b1};
                *(float2*)(yout + (size_t)row1 * D + col) = o;
            }
            if (row2 < N_NODES) {
                float2 o = {acc[mi][ni][2] + b0, acc[mi][ni][3] + b1};
                *(float2*)(yout + (size_t)row2 * D + col) = o;
            }
        }
}

// ---------------- edge GEMM-scatter: y[dst] += scale * (x_eff[src] @ W_rel) ----
__global__ void __launch_bounds__(256)
k_edge(int flip, int dorelu, const float* __restrict__ Wbase) {
    const float* xin = flip ? g_y : g_x;
    float* yout = flip ? g_x : g_y;

    __shared__ uint32_t sA[128 * SA_STRIDE];
    __shared__ uint32_t sB[16 * SB_STRIDE];
    __shared__ float sStage[32 * 132];
    __shared__ int sSrc[128];
    __shared__ int sDst[128];
    __shared__ float sScale[128];
    __shared__ int sRel;

    int tid = threadIdx.x;
    int lane = tid & 31;
    int w = tid >> 5;
    int g = lane >> 2, tg = lane & 3;
    int rm = (w & 1) * 64, cn = (w >> 1) * 32;
    int row0 = blockIdx.x * 128;

    if (tid < 128) {
        sSrc[tid] = g_esrc[row0 + tid];
        sDst[tid] = g_edst[row0 + tid];
        sScale[tid] = g_escale[row0 + tid];
    }
    if (tid == 0) {
        int r = 0;
#pragma unroll
        for (int i = 1; i < R; i++)
            if (row0 >= g_poff[i]) r = i;
        sRel = r;
    }
    __syncthreads();
    const float* W = Wbase + (size_t)sRel * D * D;

    float acc[4][4][4];
#pragma unroll
    for (int mi = 0; mi < 4; mi++)
#pragma unroll
        for (int ni = 0; ni < 4; ni++)
#pragma unroll
            for (int c = 0; c < 4; c++) acc[mi][ni][c] = 0.f;

    for (int kb = 0; kb < 8; kb++) {
#pragma unroll
        for (int h = 0; h < 2; h++) {
            int q = tid + h * 256;
            int m = q >> 2, k4 = q & 3;
            float4 v = *(const float4*)(xin + (size_t)sSrc[m] * D + kb * 16 + k4 * 4);
            if (dorelu) {
                v.x = fmaxf(v.x, 0.f); v.y = fmaxf(v.y, 0.f);
                v.z = fmaxf(v.z, 0.f); v.w = fmaxf(v.w, 0.f);
            }
            uint4 t4 = {f2tf32(v.x), f2tf32(v.y), f2tf32(v.z), f2tf32(v.w)};
            ((uint4*)(sA + m * SA_STRIDE))[k4] = t4;
        }
#pragma unroll
        for (int h = 0; h < 2; h++) {
            int q = tid + h * 256;
            int k = q >> 5, n4 = q & 31;
            float4 v = *(const float4*)(W + (size_t)(kb * 16 + k) * D + n4 * 4);
            uint4 t4 = {f2tf32(v.x), f2tf32(v.y), f2tf32(v.z), f2tf32(v.w)};
            ((uint4*)(sB + k * SB_STRIDE))[n4] = t4;
        }
        __syncthreads();
#pragma unroll
        for (int kk = 0; kk < 16; kk += 8) {
            uint32_t af[4][4];
#pragma unroll
            for (int mi = 0; mi < 4; mi++) {
                int mrow = rm + mi * 16 + g;
                af[mi][0] = sA[mrow * SA_STRIDE + kk + tg];
                af[mi][1] = sA[(mrow + 8) * SA_STRIDE + kk + tg];
                af[mi][2] = sA[mrow * SA_STRIDE + kk + tg + 4];
                af[mi][3] = sA[(mrow + 8) * SA_STRIDE + kk + tg + 4];
            }
            uint32_t bf[4][2];
#pragma unroll
            for (int ni = 0; ni < 4; ni++) {
                int ncol = cn + ni * 8 + g;
                bf[ni][0] = sB[(kk + tg) * SB_STRIDE + ncol];
                bf[ni][1] = sB[(kk + tg + 4) * SB_STRIDE + ncol];
            }
#pragma unroll
            for (int mi = 0; mi < 4; mi++)
#pragma unroll
                for (int ni = 0; ni < 4; ni++)
                    MMA_TF32(acc[mi][ni], af[mi][0], af[mi][1], af[mi][2],
                             af[mi][3], bf[ni][0], bf[ni][1]);
        }
        __syncthreads();
    }

    // epilogue: stage 32 edge-rows at a time, emit coalesced float4 RED
#pragma unroll
    for (int ph = 0; ph < 4; ph++) {
        if (rm == ((ph >> 1) << 6)) {
            int mi0 = (ph & 1) * 2;
#pragma unroll
            for (int mm = 0; mm < 2; mm++) {
                int mi = mi0 + mm;
                int r1 = mm * 16 + g;
#pragma unroll
                for (int ni = 0; ni < 4; ni++) {
                    int col = cn + ni * 8 + 2 * tg;
                    sStage[r1 * 132 + col] = acc[mi][ni][0];
                    sStage[r1 * 132 + col + 1] = acc[mi][ni][1];
                    sStage[(r1 + 8) * 132 + col] = acc[mi][ni][2];
                    sStage[(r1 + 8) * 132 + col + 1] = acc[mi][ni][3];
                }
            }
        }
        __syncthreads();
        int rbase = ph * 32;
#pragma unroll
        for (int i = tid; i < 1024; i += 256) {
            int r = i >> 5, f4 = i & 31;
            float s = sScale[rbase + r];
            if (s != 0.f) {
                int dst = sDst[rbase + r];
                float4 v;
                v.x = sStage[r * 132 + f4 * 4 + 0] * s;
                v.y = sStage[r * 132 + f4 * 4 + 1] * s;
                v.z = sStage[r * 132 + f4 * 4 + 2] * s;
                v.w = sStage[r * 132 + f4 * 4 + 3] * s;
                atomicAdd((float4*)(yout + (size_t)dst * D) + f4, v);
            }
        }
        __syncthreads();
    }
}

// ---------------- global mean pool (relu applied on read) ----------------------
__global__ void k_pool(const int* __restrict__ batch) {
    const float* x = g_y;               // layer-2 output (pre-relu)
    int d = threadIdx.x;                // 128 threads == D
    int start = blockIdx.x * 256;
    if (start >= N_NODES) return;
    int end = min(start + 256, N_NODES);
    float acc = 0.f, c = 0.f;
    int curb = batch[start];
    for (int n = start; n < end; n++) {
        int bb = batch[n];
        if (bb != curb) {
            atomicAdd(&g_pool[curb * D + d], acc);
            if (d == 0) atomicAdd(&g_pcnt[curb], c);
            acc = 0.f; c = 0.f; curb = bb;
        }
        acc += fmaxf(x[(size_t)n * D + d], 0.f);
        c += 1.f;
    }
    atomicAdd(&g_pool[curb * D + d], acc);
    if (d == 0) atomicAdd(&g_pcnt[curb], c);
}

// ---------------- MLP heads ----------------------------------------------------
__global__ void k_head(const float* __restrict__ rw1, const float* __restrict__ rb1,
                       const float* __restrict__ rw2, const float* __restrict__ rb2,
                       const float* __restrict__ sw1, const float* __restrict__ sb1,
                       const float* __restrict__ sw2, const float* __restrict__ sb2,
                       float* __restrict__ out) {
    int b = blockIdx.x;
    int j = threadIdx.x;
    __shared__ float gv[128];
    __shared__ float red[4];
    float inv = 1.f / fmaxf(g_pcnt[b], 1.f);
    gv[j] = g_pool[b * D + j] * inv;
    __syncthreads();

#pragma unroll
    for (int head = 0; head < 2; head++) {
        const float* W1 = head ? sw1 : rw1;
        const float* B1 = head ? sb1 : rb1;
        const float* W2 = head ? sw2 : rw2;
        const float* B2 = head ? sb2 : rb2;
        float h = B1[j];
#pragma unroll 8
        for (int d = 0; d < D; d++) h += gv[d] * W1[d * D + j];
        h = fmaxf(h, 0.f);
        float p = h * W2[j];
#pragma unroll
        for (int o = 16; o > 0; o >>= 1) p += __shfl_down_sync(0xffffffffu, p, o);
        if ((j & 31) == 0) red[j >> 5] = p;
        __syncthreads();
        if (j == 0) out[head * B_GRAPHS + b] = red[0] + red[1] + red[2] + red[3] + B2[0];
        __syncthreads();
    }
}

// ---------------- launch --------------------------------------------------------
extern "C" void kernel_launch(void* const* d_in, const int* in_sizes, int n_in,
                              void* d_out, int out_size) {
    const int* node_type = (const int*)d_in[0];
    const int* edge_index = (const int*)d_in[1];
    const int* edge_type = (const int*)d_in[2];
    const int* batch = (const int*)d_in[3];
    const float* node_emb = (const float*)d_in[4];
    const float* rel_w = (const float*)d_in[5];
    const float* root_w = (const float*)d_in[6];
    const float* bias = (const float*)d_in[7];
    const float* risk_w1 = (const float*)d_in[8];
    const float* risk_b1 = (const float*)d_in[9];
    const float* risk_w2 = (const float*)d_in[10];
    const float* risk_b2 = (const float*)d_in[11];
    const float* safe_w1 = (const float*)d_in[12];
    const float* safe_b1 = (const float*)d_in[13];
    const float* safe_w2 = (const float*)d_in[14];
    const float* safe_b2 = (const float*)d_in[15];
    float* out = (float*)d_out;

    k_init<<<3125, 256>>>();
    k_prefill<<<(EPAD_CAP + 255) / 256, 256>>>();
    k_count<<<(N_EDGES + 255) / 256, 256>>>(edge_index, edge_type);
    k_finalize_inv<<<(N_NODES * R + 255) / 256, 256>>>();
    k_offsets<<<1, 32>>>();
    k_sort<<<(N_EDGES + 255) / 256, 256>>>(edge_index, edge_type);
    k_gather<<<(N_NODES * (D / 4) + 255) / 256, 256>>>(node_type, node_emb);

    for (int l = 0; l < L_LAYERS; l++) {
        int flip = l & 1;       // 0: in g_x -> out g_y ; 1: in g_y -> out g_x
        int dorelu = (l > 0);
        k_root<<<(N_NODES + 127) / 128, 256>>>(
            flip, dorelu, root_w + (size_t)l * D * D, bias + (size_t)l * D);
        k_edge<<<NBLK_EDGE, 256>>>(
            flip, dorelu, rel_w + (size_t)l * R * D * D);
    }

    k_pool<<<(N_NODES + 255) / 256, 128>>>(batch);
    k_head<<<B_GRAPHS, 128>>>(risk_w1, risk_b1, risk_w2, risk_b2,
                              safe_w1, safe_b1, safe_w2, safe_b2, out);
}

// round 5
// speedup vs baseline: 5.8571x; 1.2898x over previous
#include <cuda_runtime.h>
#include <math.h>
#include <stdint.h>

#define N_NODES 100000
#define N_EDGES 600000
#define D 128
#define R 8
#define B_GRAPHS 64
#define L_LAYERS 3

#define NSEG (N_NODES * R)          // 800000 (rel,dst) segments
#define EPAD_CAP 601088             // >= E + R*127, multiple of 128
#define NBLK_EDGE (EPAD_CAP / 128)  // 4696

#define SCAN_CHUNK 2048
#define SCAN_BPR ((N_NODES + SCAN_CHUNK - 1) / SCAN_CHUNK)  // 49
#define NBLK_SCAN (SCAN_BPR * R)                            // 392

// ---------------- scratch (device globals; zero-initialized at load) ----------
__device__ __align__(16) float g_x[N_NODES * D];      // 51.2 MB
__device__ __align__(16) float g_y[N_NODES * D];      // 51.2 MB
__device__ int   g_cnt[NSEG];                         // per-(rel,dst) edge count
__device__ int   g_segoff[NSEG];                      // segment base offsets
__device__ int   g_part[NBLK_SCAN];
__device__ int   g_pbase[NBLK_SCAN];
__device__ int   g_poff[R + 1];
__device__ int   g_esrc[EPAD_CAP];                    // padding slots stay 0
__device__ int   g_edst[EPAD_CAP];
__device__ float g_escale[EPAD_CAP];                  // padding slots stay 0
__device__ float g_pool[B_GRAPHS * D];
__device__ float g_pcnt[B_GRAPHS];

// ---------------- counting + scan ---------------------------------------------
__global__ void k_count(const int* __restrict__ ei, const int* __restrict__ et) {
    int e = blockIdx.x * blockDim.x + threadIdx.x;
    if (e >= N_EDGES) return;
    int t = et[e];
    int dst = ei[N_EDGES + e];
    atomicAdd(&g_cnt[t * N_NODES + dst], 1);
}

__global__ void k_scanA() {
    __shared__ int ssum[256];
    int b = blockIdx.x;
    int rel = b / SCAN_BPR, cb = b % SCAN_BPR;
    int base = rel * N_NODES + cb * SCAN_CHUNK;
    int lim = rel * N_NODES + N_NODES;
    int t = threadIdx.x;
    int s = 0;
#pragma unroll
    for (int i = 0; i < 8; i++) {
        int idx = base + t * 8 + i;
        if (idx < lim) s += g_cnt[idx];
    }
    ssum[t] = s;
    __syncthreads();
    for (int o = 128; o > 0; o >>= 1) {
        if (t < o) ssum[t] += ssum[t + o];
        __syncthreads();
    }
    if (t == 0) g_part[b] = ssum[0];
}

__global__ void k_scanB() {
    if (threadIdx.x == 0) {
        int off = 0;
        for (int r = 0; r < R; r++) {
            g_poff[r] = off;
            int tot = 0;
            for (int cb = 0; cb < SCAN_BPR; cb++) {
                g_pbase[r * SCAN_BPR + cb] = off + tot;
                tot += g_part[r * SCAN_BPR + cb];
            }
            off += ((tot + 127) >> 7) << 7;   // pad bucket to 128
        }
        g_poff[R] = off;
    }
}

__global__ void k_scanC() {
    __shared__ int sv[256];
    int b = blockIdx.x;
    int rel = b / SCAN_BPR, cb = b % SCAN_BPR;
    int base = rel * N_NODES + cb * SCAN_CHUNK;
    int lim = rel * N_NODES + N_NODES;
    int t = threadIdx.x;
    int loc[8];
    int s = 0;
#pragma unroll
    for (int i = 0; i < 8; i++) {
        int idx = base + t * 8 + i;
        loc[i] = s;
        if (idx < lim) s += g_cnt[idx];
    }
    sv[t] = s;
    __syncthreads();
    for (int o = 1; o < 256; o <<= 1) {
        int add = (t >= o) ? sv[t - o] : 0;
        __syncthreads();
        sv[t] += add;
        __syncthreads();
    }
    int texcl = sv[t] - s;
    int bb = g_pbase[b];
#pragma unroll
    for (int i = 0; i < 8; i++) {
        int idx = base + t * 8 + i;
        if (idx < lim) g_segoff[idx] = bb + texcl + loc[i];
    }
}

// place edges sorted by (rel, dst)
__global__ void k_sort(const int* __restrict__ ei, const int* __restrict__ et) {
    int e = blockIdx.x * blockDim.x + threadIdx.x;
    if (e >= N_EDGES) return;
    int t = et[e];
    int src = ei[e];
    int dst = ei[N_EDGES + e];
    int seg = t * N_NODES + dst;
    int cnt = g_cnt[seg];
    int pos = atomicAdd(&g_segoff[seg], 1);
    g_esrc[pos] = src;
    g_edst[pos] = dst;
    g_escale[pos] = 1.0f / (float)max(cnt, 1);
}

// x = node_emb[node_type]
__global__ void k_gather(const int* __restrict__ node_type,
                         const float* __restrict__ node_emb) {
    int idx = blockIdx.x * blockDim.x + threadIdx.x;
    if (idx >= N_NODES * (D / 4)) return;
    int n = idx >> 5;
    int f = idx & 31;
    ((float4*)g_x)[idx] =
        ((const float4*)(node_emb + (size_t)node_type[n] * D))[f];
}

// ---------------- tf32 helpers --------------------------------------------------
#define SA_STRIDE 20
#define SB_STRIDE 136

__device__ __forceinline__ uint32_t f2tf32(float x) {
    uint32_t r;
    asm("cvt.rna.tf32.f32 %0, %1;" : "=r"(r) : "f"(x));
    return r;
}

__device__ __forceinline__ uint4 cvt4(float4 v, int dorelu) {
    if (dorelu) {
        v.x = fmaxf(v.x, 0.f); v.y = fmaxf(v.y, 0.f);
        v.z = fmaxf(v.z, 0.f); v.w = fmaxf(v.w, 0.f);
    }
    uint4 t4;
    t4.x = f2tf32(v.x); t4.y = f2tf32(v.y);
    t4.z = f2tf32(v.z); t4.w = f2tf32(v.w);
    return t4;
}

#define MMA_TF32(ac, a0, a1, a2, a3, b0, b1)                                   \
    asm volatile(                                                              \
        "mma.sync.aligned.m16n8k8.row.col.f32.tf32.tf32.f32 "                  \
        "{%0,%1,%2,%3}, {%4,%5,%6,%7}, {%8,%9}, {%0,%1,%2,%3};"                \
        : "+f"((ac)[0]), "+f"((ac)[1]), "+f"((ac)[2]), "+f"((ac)[3])           \
        : "r"(a0), "r"(a1), "r"(a2), "r"(a3), "r"(b0), "r"(b1))

// ---------------- root: y = x_eff @ Wroot + bias --------------------------------
__global__ void __launch_bounds__(256)
k_root(int flip, int dorelu, const float* __restrict__ W,
       const float* __restrict__ bias) {
    const float* xin = flip ? g_y : g_x;
    float* yout = flip ? g_x : g_y;

    __shared__ uint32_t sA[128 * SA_STRIDE];
    __shared__ uint32_t sB[16 * SB_STRIDE];
    __shared__ float sBias[128];

    int tid = threadIdx.x;
    int lane = tid & 31;
    int w = tid >> 5;
    int g = lane >> 2, tg = lane & 3;
    int rm = (w & 1) * 64, cn = (w >> 1) * 32;
    int row0 = blockIdx.x * 128;

    if (tid < 128) sBias[tid] = bias[tid];

    int mA0 = tid >> 2, k4 = tid & 3;
    int mA1 = mA0 + 64;
    int kB0 = tid >> 5, n4 = tid & 31;
    int kB1 = kB0 + 8;
    int rowA0 = min(row0 + mA0, N_NODES - 1);
    int rowA1 = min(row0 + mA1, N_NODES - 1);
    bool vA0 = (row0 + mA0) < N_NODES;
    bool vA1 = (row0 + mA1) < N_NODES;
    const float* a0p = xin + (size_t)rowA0 * D + k4 * 4;
    const float* a1p = xin + (size_t)rowA1 * D + k4 * 4;
    const float* b0p = W + (size_t)kB0 * D + n4 * 4;
    const float* b1p = W + (size_t)kB1 * D + n4 * 4;

    float acc[4][4][4];
#pragma unroll
    for (int mi = 0; mi < 4; mi++)
#pragma unroll
        for (int ni = 0; ni < 4; ni++)
#pragma unroll
            for (int c = 0; c < 4; c++) acc[mi][ni][c] = 0.f;

    float4 pa0 = *(const float4*)a0p;
    float4 pa1 = *(const float4*)a1p;
    float4 pb0 = *(const float4*)b0p;
    float4 pb1 = *(const float4*)b1p;

    for (int kb = 0; kb < 8; kb++) {
        if (!vA0) pa0 = make_float4(0.f, 0.f, 0.f, 0.f);
        if (!vA1) pa1 = make_float4(0.f, 0.f, 0.f, 0.f);
        ((uint4*)(sA + mA0 * SA_STRIDE))[k4] = cvt4(pa0, dorelu);
        ((uint4*)(sA + mA1 * SA_STRIDE))[k4] = cvt4(pa1, dorelu);
        ((uint4*)(sB + kB0 * SB_STRIDE))[n4] = cvt4(pb0, 0);
        ((uint4*)(sB + kB1 * SB_STRIDE))[n4] = cvt4(pb1, 0);
        __syncthreads();
        if (kb < 7) {
            pa0 = *(const float4*)(a0p + (kb + 1) * 16);
            pa1 = *(const float4*)(a1p + (kb + 1) * 16);
            pb0 = *(const float4*)(b0p + (size_t)(kb + 1) * 16 * D);
            pb1 = *(const float4*)(b1p + (size_t)(kb + 1) * 16 * D);
        }
#pragma unroll
        for (int kk = 0; kk < 16; kk += 8) {
            uint32_t af[4][4];
#pragma unroll
            for (int mi = 0; mi < 4; mi++) {
                int mrow = rm + mi * 16 + g;
                af[mi][0] = sA[mrow * SA_STRIDE + kk + tg];
                af[mi][1] = sA[(mrow + 8) * SA_STRIDE + kk + tg];
                af[mi][2] = sA[mrow * SA_STRIDE + kk + tg + 4];
                af[mi][3] = sA[(mrow + 8) * SA_STRIDE + kk + tg + 4];
            }
            uint32_t bf[4][2];
#pragma unroll
            for (int ni = 0; ni < 4; ni++) {
                int ncol = cn + ni * 8 + g;
                bf[ni][0] = sB[(kk + tg) * SB_STRIDE + ncol];
                bf[ni][1] = sB[(kk + tg + 4) * SB_STRIDE + ncol];
            }
#pragma unroll
            for (int mi = 0; mi < 4; mi++)
#pragma unroll
                for (int ni = 0; ni < 4; ni++)
                    MMA_TF32(acc[mi][ni], af[mi][0], af[mi][1], af[mi][2],
                             af[mi][3], bf[ni][0], bf[ni][1]);
        }
        __syncthreads();
    }

#pragma unroll
    for (int mi = 0; mi < 4; mi++)
#pragma unroll
        for (int ni = 0; ni < 4; ni++) {
            int col = cn + ni * 8 + 2 * tg;
            int row1 = row0 + rm + mi * 16 + g;
            int row2 = row1 + 8;
            float b0 = sBias[col], b1 = sBias[col + 1];
            if (row1 < N_NODES) {
                float2 o = {acc[mi][ni][0] + b0, acc[mi][ni][1] + b1};
                *(float2*)(yout + (size_t)row1 * D + col) = o;
            }
            if (row2 < N_NODES) {
                float2 o = {acc[mi][ni][2] + b0, acc[mi][ni][3] + b1};
                *(float2*)(yout + (size_t)row2 * D + col) = o;
            }
        }
}

// ---------------- edge GEMM-scatter: y[dst] += scale * (x_eff[src] @ W_rel) ----
__global__ void __launch_bounds__(256)
k_edge(int flip, int dorelu, const float* __restrict__ Wbase) {
    const float* xin = flip ? g_y : g_x;
    float* yout = flip ? g_x : g_y;

    __shared__ union {
        struct { uint32_t a[128 * SA_STRIDE]; uint32_t b[16 * SB_STRIDE]; } mm;
        float stage[128 * 132];
    } u;
    __shared__ int sSrc[128];
    __shared__ int sDst[128];
    __shared__ float sScale[128];
    __shared__ int sRel;

    int tid = threadIdx.x;
    int lane = tid & 31;
    int w = tid >> 5;
    int g = lane >> 2, tg = lane & 3;
    int rm = (w & 1) * 64, cn = (w >> 1) * 32;
    int row0 = blockIdx.x * 128;

    if (tid < 128) {
        sSrc[tid] = g_esrc[row0 + tid];
        sDst[tid] = g_edst[row0 + tid];
        sScale[tid] = g_escale[row0 + tid];
    }
    if (tid == 0) {
        int r = 0;
#pragma unroll
        for (int i = 1; i < R; i++)
            if (row0 >= g_poff[i]) r = i;
        sRel = r;
    }
    __syncthreads();
    const float* W = Wbase + (size_t)sRel * D * D;

    int mA0 = tid >> 2, k4 = tid & 3;
    int mA1 = mA0 + 64;
    int kB0 = tid >> 5, n4 = tid & 31;
    int kB1 = kB0 + 8;
    const float* a0p = xin + (size_t)sSrc[mA0] * D + k4 * 4;
    const float* a1p = xin + (size_t)sSrc[mA1] * D + k4 * 4;
    const float* b0p = W + (size_t)kB0 * D + n4 * 4;
    const float* b1p = W + (size_t)kB1 * D + n4 * 4;

    float acc[4][4][4];
#pragma unroll
    for (int mi = 0; mi < 4; mi++)
#pragma unroll
        for (int ni = 0; ni < 4; ni++)
#pragma unroll
            for (int c = 0; c < 4; c++) acc[mi][ni][c] = 0.f;

    float4 pa0 = *(const float4*)a0p;
    float4 pa1 = *(const float4*)a1p;
    float4 pb0 = *(const float4*)b0p;
    float4 pb1 = *(const float4*)b1p;

    for (int kb = 0; kb < 8; kb++) {
        ((uint4*)(u.mm.a + mA0 * SA_STRIDE))[k4] = cvt4(pa0, dorelu);
        ((uint4*)(u.mm.a + mA1 * SA_STRIDE))[k4] = cvt4(pa1, dorelu);
        ((uint4*)(u.mm.b + kB0 * SB_STRIDE))[n4] = cvt4(pb0, 0);
        ((uint4*)(u.mm.b + kB1 * SB_STRIDE))[n4] = cvt4(pb1, 0);
        __syncthreads();
        if (kb < 7) {
            pa0 = *(const float4*)(a0p + (kb + 1) * 16);
            pa1 = *(const float4*)(a1p + (kb + 1) * 16);
            pb0 = *(const float4*)(b0p + (size_t)(kb + 1) * 16 * D);
            pb1 = *(const float4*)(b1p + (size_t)(kb + 1) * 16 * D);
        }
#pragma unroll
        for (int kk = 0; kk < 16; kk += 8) {
            uint32_t af[4][4];
#pragma unroll
            for (int mi = 0; mi < 4; mi++) {
                int mrow = rm + mi * 16 + g;
                af[mi][0] = u.mm.a[mrow * SA_STRIDE + kk + tg];
                af[mi][1] = u.mm.a[(mrow + 8) * SA_STRIDE + kk + tg];
                af[mi][2] = u.mm.a[mrow * SA_STRIDE + kk + tg + 4];
                af[mi][3] = u.mm.a[(mrow + 8) * SA_STRIDE + kk + tg + 4];
            }
            uint32_t bf[4][2];
#pragma unroll
            for (int ni = 0; ni < 4; ni++) {
                int ncol = cn + ni * 8 + g;
                bf[ni][0] = u.mm.b[(kk + tg) * SB_STRIDE + ncol];
                bf[ni][1] = u.mm.b[(kk + tg + 4) * SB_STRIDE + ncol];
            }
#pragma unroll
            for (int mi = 0; mi < 4; mi++)
#pragma unroll
                for (int ni = 0; ni < 4; ni++)
                    MMA_TF32(acc[mi][ni], af[mi][0], af[mi][1], af[mi][2],
                             af[mi][3], bf[ni][0], bf[ni][1]);
        }
        __syncthreads();
    }

    // stage all 128 rows, scale folded (padding rows have scale 0 -> zeros)
#pragma unroll
    for (int mi = 0; mi < 4; mi++)
#pragma unroll
        for (int ni = 0; ni < 4; ni++) {
            int col = cn + ni * 8 + 2 * tg;
            int row1 = rm + mi * 16 + g;
            int row2 = row1 + 8;
            float s1 = sScale[row1], s2 = sScale[row2];
            u.stage[row1 * 132 + col] = acc[mi][ni][0] * s1;
            u.stage[row1 * 132 + col + 1] = acc[mi][ni][1] * s1;
            u.stage[row2 * 132 + col] = acc[mi][ni][2] * s2;
            u.stage[row2 * 132 + col + 1] = acc[mi][ni][3] * s2;
        }
    __syncthreads();

    // merged scatter: 32 f4-columns x 8 walkers of 16 sorted rows each
    {
        int col4 = tid & 31;
        int wk = tid >> 5;
        int r0 = wk * 16;
        float4 a4 = *(float4*)&u.stage[r0 * 132 + col4 * 4];
        int cur = sDst[r0];
        bool any = (sScale[r0] != 0.f);
#pragma unroll
        for (int rr = r0 + 1; rr < r0 + 16; rr++) {
            int dd = sDst[rr];
            float4 v = *(float4*)&u.stage[rr * 132 + col4 * 4];
            bool act = (sScale[rr] != 0.f);
            if (dd != cur) {
                if (any)
                    atomicAdd((float4*)(yout + (size_t)cur * D) + col4, a4);
                a4 = v;
                cur = dd;
                any = act;
            } else {
                a4.x += v.x; a4.y += v.y; a4.z += v.z; a4.w += v.w;
                any = any || act;
            }
        }
        if (any)
            atomicAdd((float4*)(yout + (size_t)cur * D) + col4, a4);
    }
}

// ---------------- global mean pool (relu applied on read) ----------------------
__global__ void k_pool(const int* __restrict__ batch) {
    const float* x = g_y;               // layer-2 output (pre-relu)
    int d = threadIdx.x;                // 128 threads == D
    int start = blockIdx.x * 256;
    if (start >= N_NODES) return;
    int end = min(start + 256, N_NODES);
    float acc = 0.f, c = 0.f;
    int curb = batch[start];
    for (int n = start; n < end; n++) {
        int bb = batch[n];
        if (bb != curb) {
            atomicAdd(&g_pool[curb * D + d], acc);
            if (d == 0) atomicAdd(&g_pcnt[curb], c);
            acc = 0.f; c = 0.f; curb = bb;
        }
        acc += fmaxf(x[(size_t)n * D + d], 0.f);
        c += 1.f;
    }
    atomicAdd(&g_pool[curb * D + d], acc);
    if (d == 0) atomicAdd(&g_pcnt[curb], c);
}

// ---------------- MLP heads ----------------------------------------------------
__global__ void k_head(const float* __restrict__ rw1, const float* __restrict__ rb1,
                       const float* __restrict__ rw2, const float* __restrict__ rb2,
                       const float* __restrict__ sw1, const float* __restrict__ sb1,
                       const float* __restrict__ sw2, const float* __restrict__ sb2,
                       float* __restrict__ out) {
    int b = blockIdx.x;
    int j = threadIdx.x;
    __shared__ float gv[128];
    __shared__ float red[4];
    float inv = 1.f / fmaxf(g_pcnt[b], 1.f);
    gv[j] = g_pool[b * D + j] * inv;
    __syncthreads();

#pragma unroll
    for (int head = 0; head < 2; head++) {
        const float* W1 = head ? sw1 : rw1;
        const float* B1 = head ? sb1 : rb1;
        const float* W2 = head ? sw2 : rw2;
        const float* B2 = head ? sb2 : rb2;
        float h = B1[j];
#pragma unroll 8
        for (int d = 0; d < D; d++) h += gv[d] * W1[d * D + j];
        h = fmaxf(h, 0.f);
        float p = h * W2[j];
#pragma unroll
        for (int o = 16; o > 0; o >>= 1) p += __shfl_down_sync(0xffffffffu, p, o);
        if ((j & 31) == 0) red[j >> 5] = p;
        __syncthreads();
        if (j == 0) out[head * B_GRAPHS + b] = red[0] + red[1] + red[2] + red[3] + B2[0];
        __syncthreads();
    }
}

// ---------------- tail: restore zero state for next graph replay ---------------
__global__ void k_tail() {
    int i = blockIdx.x * blockDim.x + threadIdx.x;
    if (i < NSEG) g_cnt[i] = 0;
    if (i < B_GRAPHS * D) g_pool[i] = 0.f;
    if (i < B_GRAPHS) g_pcnt[i] = 0.f;
}

// ---------------- launch --------------------------------------------------------
extern "C" void kernel_launch(void* const* d_in, const int* in_sizes, int n_in,
                              void* d_out, int out_size) {
    const int* node_type = (const int*)d_in[0];
    const int* edge_index = (const int*)d_in[1];
    const int* edge_type = (const int*)d_in[2];
    const int* batch = (const int*)d_in[3];
    const float* node_emb = (const float*)d_in[4];
    const float* rel_w = (const float*)d_in[5];
    const float* root_w = (const float*)d_in[6];
    const float* bias = (const float*)d_in[7];
    const float* risk_w1 = (const float*)d_in[8];
    const float* risk_b1 = (const float*)d_in[9];
    const float* risk_w2 = (const float*)d_in[10];
    const float* risk_b2 = (const float*)d_in[11];
    const float* safe_w1 = (const float*)d_in[12];
    const float* safe_b1 = (const float*)d_in[13];
    const float* safe_w2 = (const float*)d_in[14];
    const float* safe_b2 = (const float*)d_in[15];
    float* out = (float*)d_out;

    k_count<<<(N_EDGES + 255) / 256, 256>>>(edge_index, edge_type);
    k_scanA<<<NBLK_SCAN, 256>>>();
    k_scanB<<<1, 32>>>();
    k_scanC<<<NBLK_SCAN, 256>>>();
    k_sort<<<(N_EDGES + 255) / 256, 256>>>(edge_index, edge_type);
    k_gather<<<(N_NODES * (D / 4) + 255) / 256, 256>>>(node_type, node_emb);

    for (int l = 0; l < L_LAYERS; l++) {
        int flip = l & 1;       // 0: in g_x -> out g_y ; 1: in g_y -> out g_x
        int dorelu = (l > 0);
        k_root<<<(N_NODES + 127) / 128, 256>>>(
            flip, dorelu, root_w + (size_t)l * D * D, bias + (size_t)l * D);
        k_edge<<<NBLK_EDGE, 256>>>(
            flip, dorelu, rel_w + (size_t)l * R * D * D);
    }

    k_pool<<<(N_NODES + 255) / 256, 128>>>(batch);
    k_head<<<B_GRAPHS, 128>>>(risk_w1, risk_b1, risk_w2, risk_b2,
                              safe_w1, safe_b1, safe_w2, safe_b2, out);
    k_tail<<<(NSEG + 255) / 256, 256>>>();
}